// round 4
// baseline (speedup 1.0000x reference)
#include <cuda_runtime.h>

// ---------------------------------------------------------------------------
// QWTForward: bicubic 2x downsample + 16 scaled copies.
//
//   D = downsample_bicubic(image)                 (4,16,256,256)
//   LL[b, g*16+c]        = D[b,c] * sLL[g]        (4,64,256,256)
//   H [b, g*16+c, band]  = D[b,c] * sH[band][g]   (4,64,3,256,256)
//
// R3: 2 output rows per thread (6 shared input rows) + streaming stores.
// ---------------------------------------------------------------------------

#define B_    4
#define C_    16
#define HIN   512
#define WIN   512
#define HOUT  256
#define WOUT  256
#define PLANE (HOUT * WOUT)                // 65536
#define LL_TOTAL ((size_t)B_ * 64 * PLANE) // 16,777,216 floats

__device__ float g_scales[16];

__global__ void compute_scales_kernel(const float* __restrict__ gl,
                                      const float* __restrict__ gh,
                                      const float* __restrict__ fl,
                                      const float* __restrict__ fh) {
    if (threadIdx.x == 0) {
        float sg = 0.f, sh = 0.f, sfl = 0.f, sfh = 0.f;
        #pragma unroll
        for (int i = 0; i < 16; i++) {
            sg  += gl[i];
            sh  += gh[i];
            sfl += fl[i];
            sfh += fh[i];
        }
        g_scales[0]  = sg  * sg;
        g_scales[1]  = sfl * sg;
        g_scales[2]  = sg  * sfl;
        g_scales[3]  = sfl * sfl;
        g_scales[4]  = sg  * sh;
        g_scales[5]  = sfl * sh;
        g_scales[6]  = sg  * sfh;
        g_scales[7]  = sfl * sfh;
        g_scales[8]  = sh  * sg;
        g_scales[9]  = sfh * sg;
        g_scales[10] = sh  * sfl;
        g_scales[11] = sfh * sfl;
        g_scales[12] = sh  * sh;
        g_scales[13] = sfh * sh;
        g_scales[14] = sh  * sfh;
        g_scales[15] = sfh * sfh;
    }
}

__global__ __launch_bounds__(256)
void qwt_kernel(const float* __restrict__ image, float* __restrict__ out) {
    __shared__ float sc[16];
    if (threadIdx.x < 16) sc[threadIdx.x] = g_scales[threadIdx.x];
    __syncthreads();

    // Linear thread id -> (b, c, yy, x4); each thread produces output rows
    // y0=2*yy, y1=2*yy+1 at 4 consecutive output x (one float4).
    unsigned tid = blockIdx.x * blockDim.x + threadIdx.x;
    int lane = threadIdx.x & 31;
    int x4 = tid & 63;            // 64 float4 per output row; consecutive in warp
    int yy = (tid >> 6) & 127;    // output row pair
    int c  = (tid >> 13) & 15;
    int b  = tid >> 17;

    const float w0 = -0.09375f, w1 = 0.59375f, w2 = 0.59375f, w3 = -0.09375f;
    const float wv[4] = {w0, w1, w2, w3};

    const float* __restrict__ plane = image + (size_t)(b * C_ + c) * (HIN * WIN);

    // 6 input rows covering both outputs: r = 4*yy - 1 + i, i = 0..5 (clamped)
    int ry[6];
    #pragma unroll
    for (int i = 0; i < 6; i++) {
        int r = 4 * yy - 1 + i;
        ry[i] = min(max(r, 0), HIN - 1);
    }

    const int base = 8 * x4;
    const bool left_clamp  = (x4 == 0);
    const bool left_shfl   = (!left_clamp) && (lane > 0);
    const bool right_clamp = (x4 == 63);
    const bool right_shfl  = (!right_clamp) && (lane < 31);

    float a0 = 0.f, a1 = 0.f, a2 = 0.f, a3 = 0.f;   // output row y0
    float e0 = 0.f, e1 = 0.f, e2 = 0.f, e3 = 0.f;   // output row y1

    #pragma unroll
    for (int i = 0; i < 6; i++) {
        const float* __restrict__ row = plane + (size_t)ry[i] * WIN;
        const float4* __restrict__ row4 = reinterpret_cast<const float4*>(row);
        float4 bv = __ldg(row4 + 2 * x4);       // cols base .. base+3
        float4 cv = __ldg(row4 + 2 * x4 + 1);   // cols base+4 .. base+7

        float up = __shfl_up_sync(0xffffffffu, cv.w, 1);
        float dn = __shfl_down_sync(0xffffffffu, bv.x, 1);
        float vm1, vp8;
        if (left_clamp)       vm1 = bv.x;
        else if (left_shfl)   vm1 = up;
        else                  vm1 = __ldg(row + base - 1);
        if (right_clamp)      vp8 = cv.w;
        else if (right_shfl)  vp8 = dn;
        else                  vp8 = __ldg(row + base + 8);

        float h0 = w0 * vm1  + w1 * bv.x + w2 * bv.y + w3 * bv.z;
        float h1 = w0 * bv.y + w1 * bv.z + w2 * bv.w + w3 * cv.x;
        float h2 = w0 * bv.w + w1 * cv.x + w2 * cv.y + w3 * cv.z;
        float h3 = w0 * cv.y + w1 * cv.z + w2 * cv.w + w3 * vp8;

        if (i < 4) {                      // contributes to output row y0
            float wi = wv[i];
            a0 = fmaf(wi, h0, a0);
            a1 = fmaf(wi, h1, a1);
            a2 = fmaf(wi, h2, a2);
            a3 = fmaf(wi, h3, a3);
        }
        if (i >= 2) {                     // contributes to output row y1
            float wi = wv[i - 2];
            e0 = fmaf(wi, h0, e0);
            e1 = fmaf(wi, h1, e1);
            e2 = fmaf(wi, h2, e2);
            e3 = fmaf(wi, h3, e3);
        }
    }

    size_t p0 = (size_t)(2 * yy) * WOUT + (size_t)x4 * 4;  // float4-aligned
    size_t p1 = p0 + WOUT;

    #pragma unroll
    for (int g = 0; g < 4; g++) {
        size_t ch = (size_t)(b * 64 + g * 16 + c);
        {
            float s = sc[g];
            float* dst = out + ch * PLANE;
            __stcs(reinterpret_cast<float4*>(dst + p0),
                   make_float4(a0 * s, a1 * s, a2 * s, a3 * s));
            __stcs(reinterpret_cast<float4*>(dst + p1),
                   make_float4(e0 * s, e1 * s, e2 * s, e3 * s));
        }
        #pragma unroll
        for (int band = 0; band < 3; band++) {
            float s = sc[4 + band * 4 + g];
            float* dst = out + LL_TOTAL + (ch * 3 + band) * PLANE;
            __stcs(reinterpret_cast<float4*>(dst + p0),
                   make_float4(a0 * s, a1 * s, a2 * s, a3 * s));
            __stcs(reinterpret_cast<float4*>(dst + p1),
                   make_float4(e0 * s, e1 * s, e2 * s, e3 * s));
        }
    }
}

extern "C" void kernel_launch(void* const* d_in, const int* in_sizes, int n_in,
                              void* d_out, int out_size) {
    const float* image = (const float*)d_in[0];
    const float* gl    = (const float*)d_in[1];
    const float* gh    = (const float*)d_in[2];
    const float* fl    = (const float*)d_in[3];
    const float* fh    = (const float*)d_in[4];
    float* out = (float*)d_out;

    compute_scales_kernel<<<1, 32>>>(gl, gh, fl, fh);

    // total threads = B*C*(HOUT/2)*(WOUT/4) = 4*16*128*64 = 524,288
    const int threads = 256;
    const int blocks = (B_ * C_ * (HOUT / 2) * (WOUT / 4)) / threads;  // 2048
    qwt_kernel<<<blocks, threads>>>(image, out);
}

// round 6
// speedup vs baseline: 1.0734x; 1.0734x over previous
#include <cuda_runtime.h>

// ---------------------------------------------------------------------------
// QWTForward: bicubic 2x downsample + 16 scaled copies.
//
//   D = downsample_bicubic(image)                 (4,16,256,256)
//   LL[b, g*16+c]        = D[b,c] * sLL[g]        (4,64,256,256)
//   H [b, g*16+c, band]  = D[b,c] * sH[band][g]   (4,64,3,256,256)
//
// R5: single kernel. Scale sums computed SERIALLY per filter (lanes 0-3),
//     matching reference summation order exactly (the sums cancel to ~1e-8,
//     so association order is semantically significant).
// ---------------------------------------------------------------------------

#define B_    4
#define C_    16
#define HIN   512
#define WIN   512
#define HOUT  256
#define WOUT  256
#define PLANE (HOUT * WOUT)                // 65536
#define LL_TOTAL ((size_t)B_ * 64 * PLANE) // 16,777,216 floats

__global__ __launch_bounds__(256)
void qwt_kernel(const float* __restrict__ image,
                const float* __restrict__ gl,
                const float* __restrict__ gh,
                const float* __restrict__ fl,
                const float* __restrict__ fh,
                float* __restrict__ out) {
    __shared__ float sc[16];

    int lane = threadIdx.x & 31;

    // Warp 0: lanes 0-3 each serially sum one 16-tap filter IN INDEX ORDER
    // (bit-identical to a scalar loop; these sums cancel to ~1e-8 so order
    // matters). Then broadcast and form the 16 pairwise products.
    if (threadIdx.x < 32) {
        float s = 0.f;
        if (lane < 4) {
            const float* __restrict__ f =
                (lane == 0) ? gl : (lane == 1) ? gh : (lane == 2) ? fl : fh;
            #pragma unroll
            for (int i = 0; i < 16; i++) s += f[i];
        }
        float vg = __shfl_sync(0xffffffffu, s, 0);  // sum(gl)
        float vh = __shfl_sync(0xffffffffu, s, 1);  // sum(gh)
        float vl = __shfl_sync(0xffffffffu, s, 2);  // sum(fl)
        float vf = __shfl_sync(0xffffffffu, s, 3);  // sum(fh)
        if (lane < 16) {
            int t = lane;
            bool hiA = (t >= 8);          // first-factor family: {sg,sfl} vs {sh,sfh}
            bool hiB = (t >> 2) & 1;      // second-factor family
            float first  = (t & 1)        ? (hiA ? vf : vl) : (hiA ? vh : vg);
            float second = ((t >> 1) & 1) ? (hiB ? vf : vl) : (hiB ? vh : vg);
            sc[t] = first * second;
        }
    }
    __syncthreads();

    // Linear thread id -> (b, c, y, x4); x4 selects 4 consecutive output x.
    unsigned tid = blockIdx.x * blockDim.x + threadIdx.x;
    int x4 = tid & 63;          // 64 float4 per row; consecutive within warp
    int y  = (tid >> 6) & 255;
    int c  = (tid >> 14) & 15;
    int b  = tid >> 18;

    const float w0 = -0.09375f, w1 = 0.59375f, w2 = 0.59375f, w3 = -0.09375f;
    const float wv[4] = {w0, w1, w2, w3};

    const float* __restrict__ plane = image + (size_t)(b * C_ + c) * (HIN * WIN);

    // Input rows (clamped)
    int ry[4];
    #pragma unroll
    for (int i = 0; i < 4; i++) {
        int r = 2 * y - 1 + i;
        ry[i] = min(max(r, 0), HIN - 1);
    }

    const int base = 8 * x4;
    const bool left_clamp  = (x4 == 0);
    const bool left_shfl   = (!left_clamp) && (lane > 0);
    const bool right_clamp = (x4 == 63);
    const bool right_shfl  = (!right_clamp) && (lane < 31);
    const bool left_load   = (!left_clamp) && (lane == 0);
    const bool right_load  = (!right_clamp) && (lane == 31);

    // ---- Front-batch all vector loads (8 independent LDG.128) ----
    float4 bv[4], cv[4];
    #pragma unroll
    for (int i = 0; i < 4; i++) {
        const float4* __restrict__ row4 =
            reinterpret_cast<const float4*>(plane + (size_t)ry[i] * WIN);
        bv[i] = __ldg(row4 + 2 * x4);       // cols base .. base+3
        cv[i] = __ldg(row4 + 2 * x4 + 1);   // cols base+4 .. base+7
    }
    // Edge scalar halo loads (only lanes 0/31 mid-row actually load)
    float lm[4], rm[4];
    #pragma unroll
    for (int i = 0; i < 4; i++) {
        const float* __restrict__ row = plane + (size_t)ry[i] * WIN;
        lm[i] = left_load  ? __ldg(row + base - 1) : 0.f;
        rm[i] = right_load ? __ldg(row + base + 8) : 0.f;
    }

    // ---- Shuffle halos + horizontal/vertical convolution ----
    float d0 = 0.f, d1 = 0.f, d2 = 0.f, d3 = 0.f;
    #pragma unroll
    for (int i = 0; i < 4; i++) {
        float up = __shfl_up_sync(0xffffffffu, cv[i].w, 1);
        float dn = __shfl_down_sync(0xffffffffu, bv[i].x, 1);
        float vm1 = left_clamp  ? bv[i].x : (left_shfl  ? up : lm[i]);
        float vp8 = right_clamp ? cv[i].w : (right_shfl ? dn : rm[i]);

        float h0 = w0 * vm1      + w1 * bv[i].x + w2 * bv[i].y + w3 * bv[i].z;
        float h1 = w0 * bv[i].y  + w1 * bv[i].z + w2 * bv[i].w + w3 * cv[i].x;
        float h2 = w0 * bv[i].w  + w1 * cv[i].x + w2 * cv[i].y + w3 * cv[i].z;
        float h3 = w0 * cv[i].y  + w1 * cv[i].z + w2 * cv[i].w + w3 * vp8;

        float wi = wv[i];
        d0 = fmaf(wi, h0, d0);
        d1 = fmaf(wi, h1, d1);
        d2 = fmaf(wi, h2, d2);
        d3 = fmaf(wi, h3, d3);
    }

    size_t p = (size_t)y * WOUT + (size_t)x4 * 4;   // float4-aligned pixel offset

    // LL: out[(b*64 + g*16 + c)*PLANE + p]
    // H : out[LL_TOTAL + ((b*64 + g*16 + c)*3 + band)*PLANE + p]
    #pragma unroll
    for (int g = 0; g < 4; g++) {
        size_t ch = (size_t)(b * 64 + g * 16 + c);
        {
            float s = sc[g];
            __stcs(reinterpret_cast<float4*>(out + ch * PLANE + p),
                   make_float4(d0 * s, d1 * s, d2 * s, d3 * s));
        }
        #pragma unroll
        for (int band = 0; band < 3; band++) {
            float s = sc[4 + band * 4 + g];
            __stcs(reinterpret_cast<float4*>(out + LL_TOTAL + (ch * 3 + band) * PLANE + p),
                   make_float4(d0 * s, d1 * s, d2 * s, d3 * s));
        }
    }
}

extern "C" void kernel_launch(void* const* d_in, const int* in_sizes, int n_in,
                              void* d_out, int out_size) {
    const float* image = (const float*)d_in[0];
    const float* gl    = (const float*)d_in[1];
    const float* gh    = (const float*)d_in[2];
    const float* fl    = (const float*)d_in[3];
    const float* fh    = (const float*)d_in[4];
    float* out = (float*)d_out;

    // total threads = B*C*HOUT*(WOUT/4) = 4*16*256*64 = 1,048,576
    const int threads = 256;
    const int blocks = (B_ * C_ * HOUT * (WOUT / 4)) / threads;  // 4096
    qwt_kernel<<<blocks, threads>>>(image, gl, gh, fl, fh, out);
}